// round 2
// baseline (speedup 1.0000x reference)
#include <cuda_runtime.h>
#include <math.h>

#define DEVFN __device__ __forceinline__

constexpr int Bb = 8, Ss = 2048, Dd = 1024, Zz = 128, Hh = 2048, Nn = 16, II = 4096, MPc = 2048;
constexpr int SB = Ss * Bb;                 // 16384 tokens
constexpr float EPS = 1e-3f;
constexpr float SCALING = 0.08838834764831843f;  // Z^-0.5

// ---------------- scratch (device globals; no allocations allowed) ----------------
__device__ float g_xn[(size_t)SB * Dd];     // LN(x), (S,B,D) rows m=s*B+b
__device__ float g_mx[(size_t)SB * Dd];     // silu(ema), same layout
__device__ float g_u [(size_t)SB * Dd];
__device__ float g_hx[(size_t)SB * Dd];
__device__ float g_q [(size_t)Bb * Ss * Zz];   // (B,S,Z)
__device__ float g_k [(size_t)Bb * Ss * Zz];   // (B,S,Z)
__device__ float g_vb[(size_t)Bb * Ss * Hh];   // (B,S,H)
__device__ float g_r [(size_t)SB * Hh];        // (S,B,H) rows m
__device__ float g_sc[(size_t)Bb * Ss * Ss];   // attention scores (B,S,S)
__device__ float g_hb[(size_t)Bb * Ss * Hh];   // attn @ v, (B,S,H)
__device__ float g_hr[(size_t)SB * Hh];        // h*r, (S,B,H) rows m
__device__ float g_h2[(size_t)SB * Dd];        // silu(hx + hr@h_w + h_b)
__device__ float g_ol[(size_t)SB * Dd];        // LN(gated), rows b*S+s  (B,S,D)
__device__ float g_in[(size_t)SB * II];        // relu FFN inner

// ---------------- helpers ----------------
DEVFN float sigm(float x) { return 1.f / (1.f + __expf(-x)); }
DEVFN float silu(float x) { return x / (1.f + __expf(-x)); }

DEVFN float warpSum(float v) {
#pragma unroll
    for (int o = 16; o; o >>= 1) v += __shfl_xor_sync(0xffffffffu, v, o);
    return v;
}
DEVFN float warpMax(float v) {
#pragma unroll
    for (int o = 16; o; o >>= 1) v = fmaxf(v, __shfl_xor_sync(0xffffffffu, v, o));
    return v;
}
// blockDim.x == 256 assumed for all block reductions
DEVFN void blockSum2(float& a, float& b) {
    __shared__ float sa[8], sb[8];
    float wa = warpSum(a), wb = warpSum(b);
    if ((threadIdx.x & 31) == 0) { sa[threadIdx.x >> 5] = wa; sb[threadIdx.x >> 5] = wb; }
    __syncthreads();
    a = 0.f; b = 0.f;
#pragma unroll
    for (int i = 0; i < 8; i++) { a += sa[i]; b += sb[i]; }
    __syncthreads();
}
DEVFN float blockSum1(float v) {
    __shared__ float s[8];
    float w = warpSum(v);
    if ((threadIdx.x & 31) == 0) s[threadIdx.x >> 5] = w;
    __syncthreads();
    float r = 0.f;
#pragma unroll
    for (int i = 0; i < 8; i++) r += s[i];
    __syncthreads();
    return r;
}
DEVFN float blockMax1(float v) {
    __shared__ float s[8];
    float w = warpMax(v);
    if ((threadIdx.x & 31) == 0) s[threadIdx.x >> 5] = w;
    __syncthreads();
    float r = s[0];
#pragma unroll
    for (int i = 1; i < 8; i++) r = fmaxf(r, s[i]);
    __syncthreads();
    return r;
}

// packed f32x2 FMA (B300; ptxas never auto-fuses — PTX only)
DEVFN unsigned long long pack2(float x, float y) {
    unsigned long long r;
    asm("mov.b64 %0, {%1,%2};" : "=l"(r) : "f"(x), "f"(y));
    return r;
}
DEVFN void fma2(unsigned long long& d, unsigned long long a, unsigned long long b) {
    asm("fma.rn.f32x2 %0, %1, %2, %0;" : "+l"(d) : "l"(a), "l"(b));
}
DEVFN float2 unpack2(unsigned long long v) {
    float2 r;
    asm("mov.b64 {%0,%1}, %2;" : "=f"(r.x), "=f"(r.y) : "l"(v));
    return r;
}

// ---------------- LN1: xn = LN(x), write transposed to (S,B,D) ----------------
__global__ __launch_bounds__(256) void k_ln1(const float* __restrict__ x,
                                             const float* __restrict__ sc,
                                             const float* __restrict__ bi) {
    int m = blockIdx.x;            // b*S + s  (x layout)
    int b = m / Ss, s = m % Ss;
    const float* xr = x + (size_t)m * Dd;
    int t = threadIdx.x;
    float v[4]; float su = 0.f, sq = 0.f;
#pragma unroll
    for (int i = 0; i < 4; i++) { float f = xr[t + 256 * i]; v[i] = f; su += f; sq += f * f; }
    blockSum2(su, sq);
    float mu  = su * (1.f / Dd);
    float inv = rsqrtf(sq * (1.f / Dd) - mu * mu + EPS);
    float* o = g_xn + (size_t)(s * Bb + b) * Dd;
#pragma unroll
    for (int i = 0; i < 4; i++) { int d = t + 256 * i; o[d] = (v[i] - mu) * inv * sc[d] + bi[d]; }
}

// ---------------- EMA: 16-state recurrence scan, one half-warp per (b,d) ----------------
__global__ __launch_bounds__(256) void k_ema(const float* __restrict__ de,
                                             const float* __restrict__ al,
                                             const float* __restrict__ be,
                                             const float* __restrict__ ga,
                                             const float* __restrict__ om) {
    int t = threadIdx.x;
    int lane = t & 15;
    int P = blockIdx.x * 16 + (t >> 4);   // 0..8191 = b*D + d
    int b = P / Dd, d = P % Dd;
    int pi = d * Nn + lane;
    float p    = sigm(de[pi]);
    float q    = 1.f - p * sigm(al[pi]);
    float coef = p * be[pi] * ga[pi] * 0.25f;   // 1/sqrt(16)
    float w = om[d];
    const float* xp = g_xn + (size_t)b * Dd + d;
    float*       op = g_mx + (size_t)b * Dd + d;
    float s = 0.f;
    for (int l = 0; l < Ss; l++) {
        float xv = xp[(size_t)l * (Bb * Dd)];
        s = fmaf(q, s, xv);
        float r = coef * s;
        r += __shfl_xor_sync(0xffffffffu, r, 1);
        r += __shfl_xor_sync(0xffffffffu, r, 2);
        r += __shfl_xor_sync(0xffffffffu, r, 4);
        r += __shfl_xor_sync(0xffffffffu, r, 8);
        if (lane == 0) op[(size_t)l * (Bb * Dd)] = silu(r + xv * w);
    }
}

// ---------------- GEMM (128x128x16, f32x2, fused epilogues) ----------------
struct GemmP {
    const float* A; const float* Bm;
    const float* bias; const float* aux1; const float* aux2;
    float* out;
    int K, N;
    long long sA, sB;
};

enum { EP_V = 0, EP_BASE, EP_SC, EP_HB, EP_H2, EP_RELU, EP_FIN };

template<int EP>
DEVFN void epi(const GemmP& p, int bz, int m, int n, float acc) {
    if (EP == EP_V) {
        float v = silu(acc + p.bias[n]);
        int s = m >> 3, b = m & 7;
        g_vb[((size_t)b * Ss + s) * Hh + n] = v;
    } else if (EP == EP_BASE) {
        float a = acc + p.bias[n];
        if (n < Dd) {
            g_u[(size_t)m * Dd + n] = sigm(a);
        } else if (n < Dd + Zz) {
            float z = silu(a); int zi = n - Dd;
            int s = m >> 3, b = m & 7;
            size_t o = ((size_t)b * Ss + s) * Zz + zi;
            g_q[o] = z * p.aux1[zi]      + p.aux2[zi];
            g_k[o] = z * p.aux1[Zz + zi] + p.aux2[Zz + zi];
        } else if (n < Dd + Zz + Hh) {
            g_r[(size_t)m * Hh + (n - Dd - Zz)] = silu(a);
        } else {
            g_hx[(size_t)m * Dd + (n - Dd - Zz - Hh)] = a;
        }
    } else if (EP == EP_SC) {
        g_sc[((size_t)bz * Ss + m) * Ss + n] = acc * SCALING + p.aux1[MPc - 1 + n - m];
    } else if (EP == EP_HB) {
        g_hb[((size_t)bz * Ss + m) * Hh + n] = acc;
    } else if (EP == EP_H2) {
        g_h2[(size_t)m * Dd + n] = silu(acc + p.bias[n] + p.aux1[(size_t)m * Dd + n]);
    } else if (EP == EP_RELU) {
        g_in[(size_t)m * II + n] = fmaxf(acc + p.bias[n], 0.f);
    } else { // EP_FIN
        p.out[(size_t)m * Dd + n] = acc + p.bias[n] + p.aux1[(size_t)m * Dd + n];
    }
}

template<int EP, bool TB>
__global__ __launch_bounds__(256) void k_gemm(GemmP p) {
    __shared__ float As[16][132];
    __shared__ float Bs[16][132];
    int bz = blockIdx.z;
    const float* A  = p.A  + (size_t)bz * p.sA;
    const float* Bm = p.Bm + (size_t)bz * p.sB;
    int m0 = blockIdx.y * 128, n0 = blockIdx.x * 128;
    int t = threadIdx.x;
    int aR = t >> 2, aC = (t & 3) * 4;
    int bR = t >> 5, bC = (t & 31) * 4;
    unsigned long long acc[8][4];
#pragma unroll
    for (int i = 0; i < 8; i++)
#pragma unroll
        for (int j = 0; j < 4; j++) acc[i][j] = 0ull;
    int tx = t & 15, ty = t >> 4;

    for (int k0 = 0; k0 < p.K; k0 += 16) {
#pragma unroll
        for (int i = 0; i < 2; i++) {
            int r = aR + i * 64;
            float4 a4 = *(const float4*)(A + (size_t)(m0 + r) * p.K + k0 + aC);
            As[aC][r] = a4.x; As[aC + 1][r] = a4.y; As[aC + 2][r] = a4.z; As[aC + 3][r] = a4.w;
        }
        if (TB) {
#pragma unroll
            for (int i = 0; i < 2; i++) {
                int r = aR + i * 64;
                float4 b4 = *(const float4*)(Bm + (size_t)(n0 + r) * p.K + k0 + aC);
                Bs[aC][r] = b4.x; Bs[aC + 1][r] = b4.y; Bs[aC + 2][r] = b4.z; Bs[aC + 3][r] = b4.w;
            }
        } else {
#pragma unroll
            for (int i = 0; i < 2; i++) {
                int r = bR + i * 8;
                *(float4*)&Bs[r][bC] = *(const float4*)(Bm + (size_t)(k0 + r) * p.N + n0 + bC);
            }
        }
        __syncthreads();
#pragma unroll
        for (int k = 0; k < 16; k++) {
            float4 a0 = *(const float4*)&As[k][ty * 8];
            float4 a1 = *(const float4*)&As[k][ty * 8 + 4];
            ulonglong2 b0 = *(const ulonglong2*)&Bs[k][tx * 8];
            ulonglong2 b1 = *(const ulonglong2*)&Bs[k][tx * 8 + 4];
            unsigned long long bb[4] = { b0.x, b0.y, b1.x, b1.y };
            float ar[8] = { a0.x, a0.y, a0.z, a0.w, a1.x, a1.y, a1.z, a1.w };
#pragma unroll
            for (int i = 0; i < 8; i++) {
                unsigned long long ai = pack2(ar[i], ar[i]);
#pragma unroll
                for (int j = 0; j < 4; j++) fma2(acc[i][j], ai, bb[j]);
            }
        }
        __syncthreads();
    }

    int gm = m0 + ty * 8, gn = n0 + tx * 8;
#pragma unroll
    for (int i = 0; i < 8; i++)
#pragma unroll
        for (int j = 0; j < 4; j++) {
            float2 v = unpack2(acc[i][j]);
            epi<EP>(p, bz, gm + i, gn + 2 * j,     v.x);
            epi<EP>(p, bz, gm + i, gn + 2 * j + 1, v.y);
        }
}

// ---------------- softmax over rows of 2048 ----------------
__global__ __launch_bounds__(256) void k_softmax() {
    size_t row = blockIdx.x;
    float* rp = g_sc + row * Ss;
    int t = threadIdx.x;
    float v[8]; float mx = -1e30f;
#pragma unroll
    for (int i = 0; i < 8; i++) { v[i] = rp[t + 256 * i]; mx = fmaxf(mx, v[i]); }
    mx = blockMax1(mx);
    float su = 0.f;
#pragma unroll
    for (int i = 0; i < 8; i++) { v[i] = __expf(v[i] - mx); su += v[i]; }
    su = blockSum1(su);
    float inv = 1.f / su;
#pragma unroll
    for (int i = 0; i < 8; i++) rp[t + 256 * i] = v[i] * inv;
}

// ---------------- hr = h (permuted) * r ----------------
__global__ __launch_bounds__(256) void k_hr() {
    size_t i = ((size_t)blockIdx.x * blockDim.x + threadIdx.x) * 4;
    size_t m = i / Hh; int h = (int)(i % Hh);
    int s = (int)(m >> 3), b = (int)(m & 7);
    float4 hb4 = *(const float4*)&g_hb[((size_t)b * Ss + s) * Hh + h];
    float4 r4  = *(const float4*)&g_r[i];
    float4 o;
    o.x = hb4.x * r4.x; o.y = hb4.y * r4.y; o.z = hb4.z * r4.z; o.w = hb4.w * r4.w;
    *(float4*)&g_hr[i] = o;
}

// ---------------- gate + LN2: out = LN(xn + u*(h2 - xn)), write (B,S,D) ----------------
__global__ __launch_bounds__(256) void k_gateln(const float* __restrict__ sc,
                                                const float* __restrict__ bi) {
    int m = blockIdx.x;            // s*B + b
    int s = m >> 3, b = m & 7;
    int t = threadIdx.x;
    size_t base = (size_t)m * Dd;
    float g[4]; float su = 0.f, sq = 0.f;
#pragma unroll
    for (int i = 0; i < 4; i++) {
        int d = t + 256 * i;
        float xn = g_xn[base + d];
        float val = xn + g_u[base + d] * (g_h2[base + d] - xn);
        g[i] = val; su += val; sq += val * val;
    }
    blockSum2(su, sq);
    float mu  = su * (1.f / Dd);
    float inv = rsqrtf(sq * (1.f / Dd) - mu * mu + EPS);
    float* o = g_ol + ((size_t)b * Ss + s) * Dd;
#pragma unroll
    for (int i = 0; i < 4; i++) { int d = t + 256 * i; o[d] = (g[i] - mu) * inv * sc[d] + bi[d]; }
}

// ---------------- launch ----------------
extern "C" void kernel_launch(void* const* d_in, const int* in_sizes, int n_in,
                              void* d_out, int out_size) {
    (void)in_sizes; (void)n_in; (void)out_size;
    const float* x    = (const float*)d_in[0];
    const float* ln_s = (const float*)d_in[1];
    const float* ln_b = (const float*)d_in[2];
    const float* v_w  = (const float*)d_in[3];
    const float* v_b  = (const float*)d_in[4];
    const float* mx_w = (const float*)d_in[5];
    const float* mx_b = (const float*)d_in[6];
    const float* h_w  = (const float*)d_in[7];
    const float* h_b  = (const float*)d_in[8];
    const float* gamma= (const float*)d_in[9];
    const float* beta = (const float*)d_in[10];
    const float* rel  = (const float*)d_in[11];
    const float* e_d  = (const float*)d_in[12];
    const float* e_a  = (const float*)d_in[13];
    const float* e_b  = (const float*)d_in[14];
    const float* e_g  = (const float*)d_in[15];
    const float* e_o  = (const float*)d_in[16];
    const float* f_s  = (const float*)d_in[17];
    const float* f_b  = (const float*)d_in[18];
    const float* w1   = (const float*)d_in[19];
    const float* b1   = (const float*)d_in[20];
    const float* w2   = (const float*)d_in[21];
    const float* b2   = (const float*)d_in[22];

    float *p_xn, *p_mx, *p_q, *p_k, *p_vb, *p_sc, *p_hr, *p_hx, *p_ol, *p_in;
    cudaGetSymbolAddress((void**)&p_xn, g_xn);
    cudaGetSymbolAddress((void**)&p_mx, g_mx);
    cudaGetSymbolAddress((void**)&p_q,  g_q);
    cudaGetSymbolAddress((void**)&p_k,  g_k);
    cudaGetSymbolAddress((void**)&p_vb, g_vb);
    cudaGetSymbolAddress((void**)&p_sc, g_sc);
    cudaGetSymbolAddress((void**)&p_hr, g_hr);
    cudaGetSymbolAddress((void**)&p_hx, g_hx);
    cudaGetSymbolAddress((void**)&p_ol, g_ol);
    cudaGetSymbolAddress((void**)&p_in, g_in);

    // 1. LN + transpose
    k_ln1<<<SB, 256>>>(x, ln_s, ln_b);
    // 2. EMA scan
    k_ema<<<(Bb * Dd) / 16, 256>>>(e_d, e_a, e_b, e_g, e_o);
    // 3. v = silu(xn @ v_w + v_b) -> (B,S,H)
    {
        GemmP p; p.A = p_xn; p.Bm = v_w; p.bias = v_b; p.aux1 = nullptr; p.aux2 = nullptr;
        p.out = nullptr; p.K = Dd; p.N = Hh; p.sA = 0; p.sB = 0;
        k_gemm<EP_V, false><<<dim3(Hh / 128, SB / 128, 1), 256>>>(p);
    }
    // 4. base = mx @ mx_w + mx_b, split into u / (q,k) / r / hx
    {
        GemmP p; p.A = p_mx; p.Bm = mx_w; p.bias = mx_b; p.aux1 = gamma; p.aux2 = beta;
        p.out = nullptr; p.K = Dd; p.N = Dd + Zz + Hh + Dd; p.sA = 0; p.sB = 0;
        k_gemm<EP_BASE, false><<<dim3((Dd + Zz + Hh + Dd) / 128, SB / 128, 1), 256>>>(p);
    }
    // 5. scores = scaling * q @ k^T + rel_pos bias   (batched over B)
    {
        GemmP p; p.A = p_q; p.Bm = p_k; p.bias = nullptr; p.aux1 = rel; p.aux2 = nullptr;
        p.out = nullptr; p.K = Zz; p.N = Ss; p.sA = (long long)Ss * Zz; p.sB = (long long)Ss * Zz;
        k_gemm<EP_SC, true><<<dim3(Ss / 128, Ss / 128, Bb), 256>>>(p);
    }
    // 6. softmax rows
    k_softmax<<<Bb * Ss, 256>>>();
    // 7. hb = attn @ vb   (batched)
    {
        GemmP p; p.A = p_sc; p.Bm = p_vb; p.bias = nullptr; p.aux1 = nullptr; p.aux2 = nullptr;
        p.out = nullptr; p.K = Ss; p.N = Hh; p.sA = (long long)Ss * Ss; p.sB = (long long)Ss * Hh;
        k_gemm<EP_HB, false><<<dim3(Hh / 128, Ss / 128, Bb), 256>>>(p);
    }
    // 8. hr = h(permute) * r
    k_hr<<<((size_t)SB * Hh / 4) / 256, 256>>>();
    // 9. h2 = silu(hx + hr @ h_w + h_b)
    {
        GemmP p; p.A = p_hr; p.Bm = h_w; p.bias = h_b; p.aux1 = p_hx; p.aux2 = nullptr;
        p.out = nullptr; p.K = Hh; p.N = Dd; p.sA = 0; p.sB = 0;
        k_gemm<EP_H2, false><<<dim3(Dd / 128, SB / 128, 1), 256>>>(p);
    }
    // 10. gate + LN2 (writes (B,S,D) order)
    k_gateln<<<SB, 256>>>(f_s, f_b);
    // 11. inner = relu(out @ w1 + b1)
    {
        GemmP p; p.A = p_ol; p.Bm = w1; p.bias = b1; p.aux1 = nullptr; p.aux2 = nullptr;
        p.out = nullptr; p.K = Dd; p.N = II; p.sA = 0; p.sB = 0;
        k_gemm<EP_RELU, false><<<dim3(II / 128, SB / 128, 1), 256>>>(p);
    }
    // 12. final = inner @ w2 + b2 + out
    {
        GemmP p; p.A = p_in; p.Bm = w2; p.bias = b2; p.aux1 = p_ol; p.aux2 = nullptr;
        p.out = (float*)d_out; p.K = II; p.N = Dd; p.sA = 0; p.sB = 0;
        k_gemm<EP_FIN, false><<<dim3(Dd / 128, SB / 128, 1), 256>>>(p);
    }
}

// round 6
// speedup vs baseline: 1.3922x; 1.3922x over previous
#include <cuda_runtime.h>
#include <cuda_bf16.h>
#include <math.h>

#define DEVFN __device__ __forceinline__
#define DG __device__ __align__(128)

constexpr int Bb = 8, Ss = 2048, Dd = 1024, Zz = 128, Nn = 16, Hh = 2048, II = 4096, MPc = 2048;
constexpr int SB = Ss * Bb;
constexpr int NMX = Dd + Zz + Hh + Dd;  // 4224
constexpr float EPS = 1e-3f;
constexpr float SCALING = 0.08838834764831843f;

// ---------------- scratch ----------------
DG float g_xn[(size_t)SB * Dd];
DG float g_mx[(size_t)SB * Dd];
DG float g_u [(size_t)SB * Dd];
DG float g_hx[(size_t)SB * Dd];
DG float g_q [(size_t)Bb * Ss * Zz];
DG float g_k [(size_t)Bb * Ss * Zz];
DG float g_vb[(size_t)Bb * Ss * Hh];
DG float g_r [(size_t)SB * Hh];
DG float g_sc[(size_t)Bb * Ss * Ss];
DG float g_hb[(size_t)Bb * Ss * Hh];
DG float g_hr[(size_t)SB * Hh];
DG float g_h2[(size_t)SB * Dd];
DG float g_ol[(size_t)SB * Dd];
DG float g_in[(size_t)SB * II];
DG __nv_bfloat16 g_wvh[(size_t)Hh * Dd], g_wvl[(size_t)Hh * Dd];
DG __nv_bfloat16 g_whh[(size_t)Dd * Hh], g_whl[(size_t)Dd * Hh];
DG __nv_bfloat16 g_w1h[(size_t)II * Dd], g_w1l[(size_t)II * Dd];
DG __nv_bfloat16 g_w2h[(size_t)Dd * II], g_w2l[(size_t)Dd * II];

// ---------------- helpers ----------------
DEVFN float sigm(float x) { return 1.f / (1.f + __expf(-x)); }
DEVFN float silu(float x) { return x / (1.f + __expf(-x)); }
DEVFN float warpSum(float v) {
#pragma unroll
    for (int o = 16; o; o >>= 1) v += __shfl_xor_sync(~0u, v, o);
    return v;
}
DEVFN float warpMax(float v) {
#pragma unroll
    for (int o = 16; o; o >>= 1) v = fmaxf(v, __shfl_xor_sync(~0u, v, o));
    return v;
}
DEVFN void blockSum2(float& a, float& b) {
    __shared__ float sa[8], sb_[8];
    float wa = warpSum(a), wb = warpSum(b);
    if ((threadIdx.x & 31) == 0) { sa[threadIdx.x >> 5] = wa; sb_[threadIdx.x >> 5] = wb; }
    __syncthreads();
    a = b = 0.f;
#pragma unroll
    for (int i = 0; i < 8; i++) { a += sa[i]; b += sb_[i]; }
    __syncthreads();
}
DEVFN float blockSum1(float v) {
    __shared__ float s[8];
    float w = warpSum(v);
    if ((threadIdx.x & 31) == 0) s[threadIdx.x >> 5] = w;
    __syncthreads();
    float r = 0.f;
#pragma unroll
    for (int i = 0; i < 8; i++) r += s[i];
    __syncthreads();
    return r;
}
DEVFN float blockMax1(float v) {
    __shared__ float s[8];
    float w = warpMax(v);
    if ((threadIdx.x & 31) == 0) s[threadIdx.x >> 5] = w;
    __syncthreads();
    float r = s[0];
#pragma unroll
    for (int i = 1; i < 8; i++) r = fmaxf(r, s[i]);
    __syncthreads();
    return r;
}

// f32x2 packed FMA (proven R0 path)
DEVFN unsigned long long pack2(float x, float y) {
    unsigned long long r;
    asm("mov.b64 %0, {%1,%2};" : "=l"(r) : "f"(x), "f"(y));
    return r;
}
DEVFN void fma2(unsigned long long& d, unsigned long long a, unsigned long long b) {
    asm("fma.rn.f32x2 %0, %1, %2, %0;" : "+l"(d) : "l"(a), "l"(b));
}
DEVFN float2 unpack2(unsigned long long v) {
    float2 r;
    asm("mov.b64 {%0,%1}, %2;" : "=f"(r.x), "=f"(r.y) : "l"(v));
    return r;
}

DEVFN void mma16816(float* c, const unsigned* a, const unsigned* b) {
    asm volatile(
        "mma.sync.aligned.m16n8k16.row.col.f32.bf16.bf16.f32 "
        "{%0,%1,%2,%3},{%4,%5,%6,%7},{%8,%9},{%0,%1,%2,%3};"
        : "+f"(c[0]), "+f"(c[1]), "+f"(c[2]), "+f"(c[3])
        : "r"(a[0]), "r"(a[1]), "r"(a[2]), "r"(a[3]), "r"(b[0]), "r"(b[1]));
}
DEVFN unsigned smem_u32(const void* p) {
    unsigned a;
    asm("{ .reg .u64 t; cvta.to.shared.u64 t, %1; cvt.u32.u64 %0, t; }" : "=r"(a) : "l"(p));
    return a;
}

// ---------------- elementwise (proven) ----------------
__global__ __launch_bounds__(256) void k_ln1(const float* __restrict__ x,
                                             const float* __restrict__ sc,
                                             const float* __restrict__ bi) {
    int m = blockIdx.x, b = m / Ss, s = m % Ss, t = threadIdx.x;
    const float* xr = x + (size_t)m * Dd;
    float v[4], su = 0.f, sq = 0.f;
#pragma unroll
    for (int i = 0; i < 4; i++) { float f = xr[t + 256 * i]; v[i] = f; su += f; sq += f * f; }
    blockSum2(su, sq);
    float mu = su * (1.f / Dd), inv = rsqrtf(sq * (1.f / Dd) - mu * mu + EPS);
    float* o = g_xn + (size_t)(s * Bb + b) * Dd;
#pragma unroll
    for (int i = 0; i < 4; i++) { int d = t + 256 * i; o[d] = (v[i] - mu) * inv * sc[d] + bi[d]; }
}

__global__ __launch_bounds__(256) void k_ema(const float* __restrict__ de, const float* __restrict__ al,
                                             const float* __restrict__ be, const float* __restrict__ ga,
                                             const float* __restrict__ om) {
    int t = threadIdx.x, lane = t & 15;
    int P = blockIdx.x * 16 + (t >> 4), b = P / Dd, d = P % Dd;
    int pi = d * Nn + lane;
    float p = sigm(de[pi]);
    float q = 1.f - p * sigm(al[pi]);
    float coef = p * be[pi] * ga[pi] * 0.25f;
    float w = om[d];
    const float* xp = g_xn + (size_t)b * Dd + d;
    float* op = g_mx + (size_t)b * Dd + d;
    float s = 0.f;
    for (int l = 0; l < Ss; l++) {
        float xv = xp[(size_t)l * (Bb * Dd)];
        s = fmaf(q, s, xv);
        float r = coef * s;
        r += __shfl_xor_sync(~0u, r, 1);
        r += __shfl_xor_sync(~0u, r, 2);
        r += __shfl_xor_sync(~0u, r, 4);
        r += __shfl_xor_sync(~0u, r, 8);
        if (lane == 0) op[(size_t)l * (Bb * Dd)] = silu(r + xv * w);
    }
}

__global__ __launch_bounds__(256) void k_softmax() {
    float* rp = g_sc + (size_t)blockIdx.x * Ss;
    int t = threadIdx.x;
    float v[8], mx = -1e30f;
#pragma unroll
    for (int i = 0; i < 8; i++) { v[i] = rp[t + 256 * i]; mx = fmaxf(mx, v[i]); }
    mx = blockMax1(mx);
    float su = 0.f;
#pragma unroll
    for (int i = 0; i < 8; i++) { v[i] = __expf(v[i] - mx); su += v[i]; }
    su = blockSum1(su);
    float inv = 1.f / su;
#pragma unroll
    for (int i = 0; i < 8; i++) rp[t + 256 * i] = v[i] * inv;
}

__global__ __launch_bounds__(256) void k_hr() {
    size_t i = ((size_t)blockIdx.x * blockDim.x + threadIdx.x) * 4;
    size_t m = i / Hh; int h = (int)(i % Hh);
    int s = (int)(m >> 3), b = (int)(m & 7);
    float4 hb4 = *(const float4*)&g_hb[((size_t)b * Ss + s) * Hh + h];
    float4 r4  = *(const float4*)&g_r[i];
    float4 o;
    o.x = hb4.x * r4.x; o.y = hb4.y * r4.y; o.z = hb4.z * r4.z; o.w = hb4.w * r4.w;
    *(float4*)&g_hr[i] = o;
}

__global__ __launch_bounds__(256) void k_gateln(const float* __restrict__ sc,
                                                const float* __restrict__ bi) {
    int m = blockIdx.x, s = m >> 3, b = m & 7, t = threadIdx.x;
    size_t base = (size_t)m * Dd;
    float g[4], su = 0.f, sq = 0.f;
#pragma unroll
    for (int i = 0; i < 4; i++) {
        int d = t + 256 * i;
        float xn = g_xn[base + d];
        float val = xn + g_u[base + d] * (g_h2[base + d] - xn);
        g[i] = val; su += val; sq += val * val;
    }
    blockSum2(su, sq);
    float mu = su * (1.f / Dd), inv = rsqrtf(sq * (1.f / Dd) - mu * mu + EPS);
    float* o = g_ol + ((size_t)b * Ss + s) * Dd;
#pragma unroll
    for (int i = 0; i < 4; i++) { int d = t + 256 * i; o[d] = (g[i] - mu) * inv * sc[d] + bi[d]; }
}

__global__ __launch_bounds__(256) void k_wt(const float* __restrict__ W,
                                            __nv_bfloat16* __restrict__ oh,
                                            __nv_bfloat16* __restrict__ ol, int K, int N) {
    __shared__ float tl[32][33];
    int n0 = blockIdx.x * 32, k0 = blockIdx.y * 32;
    int tx = threadIdx.x & 31, ty = threadIdx.x >> 5;
#pragma unroll
    for (int i = 0; i < 4; i++) tl[ty + i * 8][tx] = W[(size_t)(k0 + ty + i * 8) * N + n0 + tx];
    __syncthreads();
#pragma unroll
    for (int i = 0; i < 4; i++) {
        int ny = ty + i * 8;
        float v = tl[tx][ny];
        size_t o = (size_t)(n0 + ny) * K + k0 + tx;
        __nv_bfloat16 h = __float2bfloat16(v);
        oh[o] = h;
        ol[o] = __float2bfloat16(v - __bfloat162float(h));
    }
}

// ================= SIMT f32x2 GEMM (verbatim R0, proven) =================
struct GemmP {
    const float* A; const float* Bm;
    const float* bias; const float* aux1; const float* aux2;
    float* out;
    int K, N;
    long long sA, sB;
};

enum { SP_BASE = 0, SP_SC, SP_HB };

template<int EP>
DEVFN void epiS(const GemmP& p, int bz, int m, int n, float acc) {
    if (EP == SP_BASE) {
        float a = acc + p.bias[n];
        if (n < Dd) {
            g_u[(size_t)m * Dd + n] = sigm(a);
        } else if (n < Dd + Zz) {
            float z = silu(a); int zi = n - Dd;
            int s = m >> 3, b = m & 7;
            size_t o = ((size_t)b * Ss + s) * Zz + zi;
            g_q[o] = z * p.aux1[zi]      + p.aux2[zi];
            g_k[o] = z * p.aux1[Zz + zi] + p.aux2[Zz + zi];
        } else if (n < Dd + Zz + Hh) {
            g_r[(size_t)m * Hh + (n - Dd - Zz)] = silu(a);
        } else {
            g_hx[(size_t)m * Dd + (n - Dd - Zz - Hh)] = a;
        }
    } else if (EP == SP_SC) {
        g_sc[((size_t)bz * Ss + m) * Ss + n] = acc * SCALING + p.aux1[MPc - 1 + n - m];
    } else { // SP_HB
        g_hb[((size_t)bz * Ss + m) * Hh + n] = acc;
    }
}

template<int EP, bool TB>
__global__ __launch_bounds__(256) void k_gemm(GemmP p) {
    __shared__ float As[16][132];
    __shared__ float Bs[16][132];
    int bz = blockIdx.z;
    const float* A  = p.A  + (size_t)bz * p.sA;
    const float* Bm = p.Bm + (size_t)bz * p.sB;
    int m0 = blockIdx.y * 128, n0 = blockIdx.x * 128;
    int t = threadIdx.x;
    int aR = t >> 2, aC = (t & 3) * 4;
    int bR = t >> 5, bC = (t & 31) * 4;
    unsigned long long acc[8][4];
#pragma unroll
    for (int i = 0; i < 8; i++)
#pragma unroll
        for (int j = 0; j < 4; j++) acc[i][j] = 0ull;
    int tx = t & 15, ty = t >> 4;

    for (int k0 = 0; k0 < p.K; k0 += 16) {
#pragma unroll
        for (int i = 0; i < 2; i++) {
            int r = aR + i * 64;
            float4 a4 = *(const float4*)(A + (size_t)(m0 + r) * p.K + k0 + aC);
            As[aC][r] = a4.x; As[aC + 1][r] = a4.y; As[aC + 2][r] = a4.z; As[aC + 3][r] = a4.w;
        }
        if (TB) {
#pragma unroll
            for (int i = 0; i < 2; i++) {
                int r = aR + i * 64;
                float4 b4 = *(const float4*)(Bm + (size_t)(n0 + r) * p.K + k0 + aC);
                Bs[aC][r] = b4.x; Bs[aC + 1][r] = b4.y; Bs[aC + 2][r] = b4.z; Bs[aC + 3][r] = b4.w;
            }
        } else {
#pragma unroll
            for (int i = 0; i < 2; i++) {
                int r = bR + i * 8;
                *(float4*)&Bs[r][bC] = *(const float4*)(Bm + (size_t)(k0 + r) * p.N + n0 + bC);
            }
        }
        __syncthreads();
#pragma unroll
        for (int k = 0; k < 16; k++) {
            float4 a0 = *(const float4*)&As[k][ty * 8];
            float4 a1 = *(const float4*)&As[k][ty * 8 + 4];
            ulonglong2 b0 = *(const ulonglong2*)&Bs[k][tx * 8];
            ulonglong2 b1 = *(const ulonglong2*)&Bs[k][tx * 8 + 4];
            unsigned long long bb[4] = { b0.x, b0.y, b1.x, b1.y };
            float ar[8] = { a0.x, a0.y, a0.z, a0.w, a1.x, a1.y, a1.z, a1.w };
#pragma unroll
            for (int i = 0; i < 8; i++) {
                unsigned long long ai = pack2(ar[i], ar[i]);
#pragma unroll
                for (int j = 0; j < 4; j++) fma2(acc[i][j], ai, bb[j]);
            }
        }
        __syncthreads();
    }

    int gm = m0 + ty * 8, gn = n0 + tx * 8;
#pragma unroll
    for (int i = 0; i < 8; i++)
#pragma unroll
        for (int j = 0; j < 4; j++) {
            float2 v = unpack2(acc[i][j]);
            epiS<EP>(p, bz, gm + i, gn + 2 * j,     v.x);
            epiS<EP>(p, bz, gm + i, gn + 2 * j + 1, v.y);
        }
}

// ================= mma.sync bf16-split GEMM (trivial epilogues only) =================
struct TG {
    const float* A;
    const __nv_bfloat16* Bh; const __nv_bfloat16* Bl;
    const float* bias;
    float* out;
    int K;
};

enum { MP_V = 0, MP_H2, MP_RELU, MP_FIN };

template<int EP>
DEVFN void epiM(const TG& p, int m, int n, float acc) {
    if (EP == MP_V) {
        float v = silu(acc + p.bias[n]);
        int s = m >> 3, b = m & 7;
        g_vb[((size_t)b * Ss + s) * Hh + n] = v;
    } else if (EP == MP_H2) {
        g_h2[(size_t)m * Dd + n] = silu(acc + p.bias[n] + g_hx[(size_t)m * Dd + n]);
    } else if (EP == MP_RELU) {
        g_in[(size_t)m * II + n] = fmaxf(acc + p.bias[n], 0.f);
    } else {
        p.out[(size_t)m * Dd + n] = acc + p.bias[n] + g_ol[(size_t)m * Dd + n];
    }
}

// CTA 128x256, warp 64x64 (8 warps), K-chunk 32 bf16, double-buffered smem.
// smem row = 16 b32 (64B); swizzle col_b32 ^ (2*(row&7)).
template<int EP>
__global__ void __launch_bounds__(256, 1) k_mgemm(TG p) {
    constexpr int TM = 128, TN = 256;
    constexpr int ASZ = TM * 64;              // 8192
    constexpr int BSZ = TN * 64;              // 16384
    constexpr int STGB = 2 * ASZ + 2 * BSZ;   // 49152
    constexpr int IA = 8;                     // TM*16/256
    constexpr int IB16 = 4;                   // TN*4/256

    extern __shared__ char sm[];
    const unsigned sb = smem_u32(sm);

    const int t = threadIdx.x, lane = t & 31, wid = t >> 5;
    const int wm = wid & 1, wn = wid >> 1;
    const int g = lane >> 2, tig = lane & 3;
    const int m0 = blockIdx.y * TM, n0 = blockIdx.x * TN;
    const float* A = p.A;
    const __nv_bfloat16* Bhp = p.Bh;
    const __nv_bfloat16* Blp = p.Bl;
    const int K = p.K;
    const int nst = K >> 5;

    float acc[4][8][4];
#pragma unroll
    for (int i = 0; i < 4; i++)
#pragma unroll
        for (int j = 0; j < 8; j++)
#pragma unroll
            for (int r = 0; r < 4; r++) acc[i][j][r] = 0.f;

    float2 rga[IA];
    uint4 rbh[IB16], rbl[IB16];

    auto LDGA = [&](int k0) {
#pragma unroll
        for (int j = 0; j < IA; j++) {
            int idx = t + 256 * j;
            int row = idx >> 4, c = idx & 15;
            rga[j] = *(const float2*)(A + (size_t)(m0 + row) * K + k0 + c * 2);
        }
    };
    auto LDGB = [&](int k0) {
#pragma unroll
        for (int j = 0; j < IB16; j++) {
            int idx = t + 256 * j;
            int row = idx >> 2, q = idx & 3;
            size_t go = (size_t)(n0 + row) * K + k0 + q * 8;
            rbh[j] = *(const uint4*)(Bhp + go);
            rbl[j] = *(const uint4*)(Blp + go);
        }
    };
    auto STSA = [&](int buf) {
        unsigned base = sb + buf * STGB;
#pragma unroll
        for (int j = 0; j < IA; j++) {
            int idx = t + 256 * j;
            int row = idx >> 4, c = idx & 15;
            unsigned off = row * 64 + ((c ^ (2 * (row & 7))) << 2);
            float2 f = rga[j];
            __nv_bfloat162 h2 = __floats2bfloat162_rn(f.x, f.y);
            float2 hf = __bfloat1622float2(h2);
            __nv_bfloat162 l2 = __floats2bfloat162_rn(f.x - hf.x, f.y - hf.y);
            unsigned uh = *(unsigned*)&h2, ul = *(unsigned*)&l2;
            asm volatile("st.shared.b32 [%0], %1;" :: "r"(base + off), "r"(uh) : "memory");
            asm volatile("st.shared.b32 [%0], %1;" :: "r"(base + ASZ + off), "r"(ul) : "memory");
        }
    };
    auto STSB = [&](int buf) {
        unsigned bh = sb + buf * STGB + 2 * ASZ;
        unsigned bl = bh + BSZ;
#pragma unroll
        for (int j = 0; j < IB16; j++) {
            int idx = t + 256 * j;
            int row = idx >> 2, q = idx & 3;
            int c0 = q * 4;
            unsigned sw = 2 * (row & 7);
            unsigned o0 = row * 64 + ((c0 ^ sw) << 2);
            unsigned o1 = row * 64 + (((c0 + 2) ^ sw) << 2);
            uint4 h = rbh[j], l = rbl[j];
            asm volatile("st.shared.v2.b32 [%0], {%1,%2};" :: "r"(bh + o0), "r"(h.x), "r"(h.y) : "memory");
            asm volatile("st.shared.v2.b32 [%0], {%1,%2};" :: "r"(bh + o1), "r"(h.z), "r"(h.w) : "memory");
            asm volatile("st.shared.v2.b32 [%0], {%1,%2};" :: "r"(bl + o0), "r"(l.x), "r"(l.y) : "memory");
            asm volatile("st.shared.v2.b32 [%0], {%1,%2};" :: "r"(bl + o1), "r"(l.z), "r"(l.w) : "memory");
        }
    };

    auto COMPUTE = [&](int buf) {
        unsigned aB = sb + buf * STGB + (wm * 64) * 64;
        unsigned bB = sb + buf * STGB + 2 * ASZ + (wn * 64) * 64;
        const unsigned sw = 2 * g;
#pragma unroll
        for (int kk = 0; kk < 2; kk++) {
            const int kb = kk * 8;
            const unsigned o0 = (((kb + tig) ^ sw) << 2);
            const unsigned o2 = (((kb + tig + 4) ^ sw) << 2);
            unsigned Ah[4][4], Al[4][4];
#pragma unroll
            for (int mi = 0; mi < 4; mi++) {
                unsigned r0 = aB + (mi * 16 + g) * 64;
                asm volatile("ld.shared.b32 %0, [%1];" : "=r"(Ah[mi][0]) : "r"(r0 + o0));
                asm volatile("ld.shared.b32 %0, [%1];" : "=r"(Ah[mi][1]) : "r"(r0 + 512 + o0));
                asm volatile("ld.shared.b32 %0, [%1];" : "=r"(Ah[mi][2]) : "r"(r0 + o2));
                asm volatile("ld.shared.b32 %0, [%1];" : "=r"(Ah[mi][3]) : "r"(r0 + 512 + o2));
                asm volatile("ld.shared.b32 %0, [%1];" : "=r"(Al[mi][0]) : "r"(r0 + ASZ + o0));
                asm volatile("ld.shared.b32 %0, [%1];" : "=r"(Al[mi][1]) : "r"(r0 + ASZ + 512 + o0));
                asm volatile("ld.shared.b32 %0, [%1];" : "=r"(Al[mi][2]) : "r"(r0 + ASZ + o2));
                asm volatile("ld.shared.b32 %0, [%1];" : "=r"(Al[mi][3]) : "r"(r0 + ASZ + 512 + o2));
            }
#pragma unroll
            for (int nh = 0; nh < 2; nh++) {
                unsigned Bhf[4][2], Blf[4][2];
#pragma unroll
                for (int nj = 0; nj < 4; nj++) {
                    unsigned rn = bB + (nh * 32 + nj * 8 + g) * 64;
                    asm volatile("ld.shared.b32 %0, [%1];" : "=r"(Bhf[nj][0]) : "r"(rn + o0));
                    asm volatile("ld.shared.b32 %0, [%1];" : "=r"(Bhf[nj][1]) : "r"(rn + o2));
                    asm volatile("ld.shared.b32 %0, [%1];" : "=r"(Blf[nj][0]) : "r"(rn + BSZ + o0));
                    asm volatile("ld.shared.b32 %0, [%1];" : "=r"(Blf[nj][1]) : "r"(rn + BSZ + o2));
                }
#pragma unroll
                for (int mi = 0; mi < 4; mi++)
#pragma unroll
                    for (int nj = 0; nj < 4; nj++) {
                        float* c = acc[mi][nh * 4 + nj];
                        mma16816(c, Ah[mi], Bhf[nj]);
                        mma16816(c, Al[mi], Bhf[nj]);
                        mma16816(c, Ah[mi], Blf[nj]);
                    }
            }
        }
    };

    LDGA(0); LDGB(0);
    STSA(0); STSB(0);
    __syncthreads();

    for (int s = 0; s < nst; s++) {
        if (s + 1 < nst) { LDGA((s + 1) * 32); LDGB((s + 1) * 32); }
        COMPUTE(s & 1);
        if (s + 1 < nst) { STSA((s + 1) & 1); STSB((s + 1) & 1); }
        __syncthreads();
    }

#pragma unroll
    for (int mi = 0; mi < 4; mi++)
#pragma unroll
        for (int ni = 0; ni < 8; ni++) {
            int row0 = m0 + wm * 64 + mi * 16 + g;
            int col0 = n0 + wn * 64 + ni * 8 + 2 * tig;
            float* c = acc[mi][ni];
            epiM<EP>(p, row0,     col0,     c[0]);
            epiM<EP>(p, row0,     col0 + 1, c[1]);
            epiM<EP>(p, row0 + 8, col0,     c[2]);
            epiM<EP>(p, row0 + 8, col0 + 1, c[3]);
        }
}

// ---------------- launch ----------------
constexpr int SM256 = 2 * (2 * 128 * 64 + 2 * 256 * 64);  // 98304

extern "C" void kernel_launch(void* const* d_in, const int* in_sizes, int n_in,
                              void* d_out, int out_size) {
    (void)in_sizes; (void)n_in; (void)out_size;
    const float* x    = (const float*)d_in[0];
    const float* ln_s = (const float*)d_in[1];
    const float* ln_b = (const float*)d_in[2];
    const float* v_w  = (const float*)d_in[3];
    const float* v_b  = (const float*)d_in[4];
    const float* mx_w = (const float*)d_in[5];
    const float* mx_b = (const float*)d_in[6];
    const float* h_w  = (const float*)d_in[7];
    const float* h_b  = (const float*)d_in[8];
    const float* gamma= (const float*)d_in[9];
    const float* beta = (const float*)d_in[10];
    const float* rel  = (const float*)d_in[11];
    const float* e_d  = (const float*)d_in[12];
    const float* e_a  = (const float*)d_in[13];
    const float* e_b  = (const float*)d_in[14];
    const float* e_g  = (const float*)d_in[15];
    const float* e_o  = (const float*)d_in[16];
    const float* f_s  = (const float*)d_in[17];
    const float* f_b  = (const float*)d_in[18];
    const float* w1   = (const float*)d_in[19];
    const float* b1   = (const float*)d_in[20];
    const float* w2   = (const float*)d_in[21];
    const float* b2   = (const float*)d_in[22];

    float *p_xn, *p_mx, *p_q, *p_k, *p_vb, *p_sc, *p_hr, *p_ol, *p_in;
    __nv_bfloat16 *p_wvh, *p_wvl, *p_whh, *p_whl, *p_w1h, *p_w1l, *p_w2h, *p_w2l;
    cudaGetSymbolAddress((void**)&p_xn, g_xn);
    cudaGetSymbolAddress((void**)&p_mx, g_mx);
    cudaGetSymbolAddress((void**)&p_q,  g_q);
    cudaGetSymbolAddress((void**)&p_k,  g_k);
    cudaGetSymbolAddress((void**)&p_vb, g_vb);
    cudaGetSymbolAddress((void**)&p_sc, g_sc);
    cudaGetSymbolAddress((void**)&p_hr, g_hr);
    cudaGetSymbolAddress((void**)&p_ol, g_ol);
    cudaGetSymbolAddress((void**)&p_in, g_in);
    cudaGetSymbolAddress((void**)&p_wvh, g_wvh);
    cudaGetSymbolAddress((void**)&p_wvl, g_wvl);
    cudaGetSymbolAddress((void**)&p_whh, g_whh);
    cudaGetSymbolAddress((void**)&p_whl, g_whl);
    cudaGetSymbolAddress((void**)&p_w1h, g_w1h);
    cudaGetSymbolAddress((void**)&p_w1l, g_w1l);
    cudaGetSymbolAddress((void**)&p_w2h, g_w2h);
    cudaGetSymbolAddress((void**)&p_w2l, g_w2l);

    cudaFuncSetAttribute(k_mgemm<MP_V>,    cudaFuncAttributeMaxDynamicSharedMemorySize, SM256);
    cudaFuncSetAttribute(k_mgemm<MP_H2>,   cudaFuncAttributeMaxDynamicSharedMemorySize, SM256);
    cudaFuncSetAttribute(k_mgemm<MP_RELU>, cudaFuncAttributeMaxDynamicSharedMemorySize, SM256);
    cudaFuncSetAttribute(k_mgemm<MP_FIN>,  cudaFuncAttributeMaxDynamicSharedMemorySize, SM256);

    // weight prep for mma GEMMs
    k_wt<<<dim3(Hh / 32, Dd / 32), 256>>>(v_w, p_wvh, p_wvl, Dd, Hh);
    k_wt<<<dim3(Dd / 32, Hh / 32), 256>>>(h_w, p_whh, p_whl, Hh, Dd);
    k_wt<<<dim3(II / 32, Dd / 32), 256>>>(w1, p_w1h, p_w1l, Dd, II);
    k_wt<<<dim3(Dd / 32, II / 32), 256>>>(w2, p_w2h, p_w2l, II, Dd);

    k_ln1<<<SB, 256>>>(x, ln_s, ln_b);
    k_ema<<<(Bb * Dd) / 16, 256>>>(e_d, e_a, e_b, e_g, e_o);

    // v = silu(xn @ v_w + v_b)  [mma]
    {
        TG p = {p_xn, p_wvh, p_wvl, v_b, nullptr, Dd};
        k_mgemm<MP_V><<<dim3(Hh / 256, SB / 128, 1), 256, SM256>>>(p);
    }
    // base = mx @ mx_w + mx_b  [SIMT, proven]
    {
        GemmP p; p.A = p_mx; p.Bm = mx_w; p.bias = mx_b; p.aux1 = gamma; p.aux2 = beta;
        p.out = nullptr; p.K = Dd; p.N = NMX; p.sA = 0; p.sB = 0;
        k_gemm<SP_BASE, false><<<dim3(NMX / 128, SB / 128, 1), 256>>>(p);
    }
    // scores  [SIMT, proven]
    {
        GemmP p; p.A = p_q; p.Bm = p_k; p.bias = nullptr; p.aux1 = rel; p.aux2 = nullptr;
        p.out = nullptr; p.K = Zz; p.N = Ss; p.sA = (long long)Ss * Zz; p.sB = (long long)Ss * Zz;
        k_gemm<SP_SC, true><<<dim3(Ss / 128, Ss / 128, Bb), 256>>>(p);
    }
    k_softmax<<<Bb * Ss, 256>>>();
    // hb = attn @ vb  [SIMT, proven]
    {
        GemmP p; p.A = p_sc; p.Bm = p_vb; p.bias = nullptr; p.aux1 = nullptr; p.aux2 = nullptr;
        p.out = nullptr; p.K = Ss; p.N = Hh; p.sA = (long long)Ss * Ss; p.sB = (long long)Ss * Hh;
        k_gemm<SP_HB, false><<<dim3(Hh / 128, Ss / 128, Bb), 256>>>(p);
    }
    k_hr<<<((size_t)SB * Hh / 4) / 256, 256>>>();
    // h2 = silu(hx + hr @ h_w + h_b)  [mma]
    {
        TG p = {p_hr, p_whh, p_whl, h_b, nullptr, Hh};
        k_mgemm<MP_H2><<<dim3(Dd / 256, SB / 128, 1), 256, SM256>>>(p);
    }
    k_gateln<<<SB, 256>>>(f_s, f_b);
    // FFN  [mma]
    {
        TG p = {p_ol, p_w1h, p_w1l, b1, nullptr, Dd};
        k_mgemm<MP_RELU><<<dim3(II / 256, SB / 128, 1), 256, SM256>>>(p);
    }
    {
        TG p = {p_in, p_w2h, p_w2l, b2, (float*)d_out, II};
        k_mgemm<MP_FIN><<<dim3(Dd / 256, SB / 128, 1), 256, SM256>>>(p);
    }
}

// round 7
// speedup vs baseline: 1.7701x; 1.2714x over previous
#include <cuda_runtime.h>
#include <cuda_bf16.h>
#include <math.h>

#define DEVFN __device__ __forceinline__
#define DG __device__ __align__(128)

constexpr int Bb = 8, Ss = 2048, Dd = 1024, Zz = 128, Nn = 16, Hh = 2048, II = 4096, MPc = 2048;
constexpr int SB = Ss * Bb;
constexpr int NMX = Dd + Zz + Hh + Dd;  // 4224
constexpr float EPS = 1e-3f;
constexpr float SCALING = 0.08838834764831843f;

// ---------------- scratch ----------------
DG float g_xn[(size_t)SB * Dd];
DG float g_mx[(size_t)SB * Dd];
DG float g_u [(size_t)SB * Dd];
DG float g_hx[(size_t)SB * Dd];
DG float g_q [(size_t)Bb * Ss * Zz];
DG float g_r [(size_t)SB * Hh];
DG float g_sc[(size_t)Bb * Ss * Ss];
DG float g_hr[(size_t)SB * Hh];
DG float g_h2[(size_t)SB * Dd];
DG float g_ol[(size_t)SB * Dd];
DG float g_in[(size_t)SB * II];
DG __nv_bfloat16 g_kh[(size_t)Bb * Ss * Zz], g_kl[(size_t)Bb * Ss * Zz];
DG __nv_bfloat16 g_vh[(size_t)Bb * Hh * Ss], g_vl[(size_t)Bb * Hh * Ss];
DG __nv_bfloat16 g_wvh[(size_t)Hh * Dd],  g_wvl[(size_t)Hh * Dd];
DG __nv_bfloat16 g_wmh[(size_t)NMX * Dd], g_wml[(size_t)NMX * Dd];
DG __nv_bfloat16 g_whh[(size_t)Dd * Hh],  g_whl[(size_t)Dd * Hh];
DG __nv_bfloat16 g_w1h[(size_t)II * Dd],  g_w1l[(size_t)II * Dd];
DG __nv_bfloat16 g_w2h[(size_t)Dd * II],  g_w2l[(size_t)Dd * II];

// ---------------- helpers ----------------
DEVFN float sigm(float x) { return 1.f / (1.f + __expf(-x)); }
DEVFN float silu(float x) { return x / (1.f + __expf(-x)); }
DEVFN float warpSum(float v) {
#pragma unroll
    for (int o = 16; o; o >>= 1) v += __shfl_xor_sync(~0u, v, o);
    return v;
}
DEVFN float warpMax(float v) {
#pragma unroll
    for (int o = 16; o; o >>= 1) v = fmaxf(v, __shfl_xor_sync(~0u, v, o));
    return v;
}
DEVFN void blockSum2(float& a, float& b) {
    __shared__ float sa[8], sb_[8];
    float wa = warpSum(a), wb = warpSum(b);
    if ((threadIdx.x & 31) == 0) { sa[threadIdx.x >> 5] = wa; sb_[threadIdx.x >> 5] = wb; }
    __syncthreads();
    a = b = 0.f;
#pragma unroll
    for (int i = 0; i < 8; i++) { a += sa[i]; b += sb_[i]; }
    __syncthreads();
}
DEVFN float blockSum1(float v) {
    __shared__ float s[8];
    float w = warpSum(v);
    if ((threadIdx.x & 31) == 0) s[threadIdx.x >> 5] = w;
    __syncthreads();
    float r = 0.f;
#pragma unroll
    for (int i = 0; i < 8; i++) r += s[i];
    __syncthreads();
    return r;
}
DEVFN float blockMax1(float v) {
    __shared__ float s[8];
    float w = warpMax(v);
    if ((threadIdx.x & 31) == 0) s[threadIdx.x >> 5] = w;
    __syncthreads();
    float r = s[0];
#pragma unroll
    for (int i = 1; i < 8; i++) r = fmaxf(r, s[i]);
    __syncthreads();
    return r;
}

DEVFN void mma16816(float* c, const unsigned* a, const unsigned* b) {
    asm volatile(
        "mma.sync.aligned.m16n8k16.row.col.f32.bf16.bf16.f32 "
        "{%0,%1,%2,%3},{%4,%5,%6,%7},{%8,%9},{%0,%1,%2,%3};"
        : "+f"(c[0]), "+f"(c[1]), "+f"(c[2]), "+f"(c[3])
        : "r"(a[0]), "r"(a[1]), "r"(a[2]), "r"(a[3]), "r"(b[0]), "r"(b[1]));
}
DEVFN unsigned smem_u32(const void* p) {
    unsigned a;
    asm("{ .reg .u64 t; cvta.to.shared.u64 t, %1; cvt.u32.u64 %0, t; }" : "=r"(a) : "l"(p));
    return a;
}

// ---------------- elementwise (proven) ----------------
__global__ __launch_bounds__(256) void k_ln1(const float* __restrict__ x,
                                             const float* __restrict__ sc,
                                             const float* __restrict__ bi) {
    int m = blockIdx.x, b = m / Ss, s = m % Ss, t = threadIdx.x;
    const float* xr = x + (size_t)m * Dd;
    float v[4], su = 0.f, sq = 0.f;
#pragma unroll
    for (int i = 0; i < 4; i++) { float f = xr[t + 256 * i]; v[i] = f; su += f; sq += f * f; }
    blockSum2(su, sq);
    float mu = su * (1.f / Dd), inv = rsqrtf(sq * (1.f / Dd) - mu * mu + EPS);
    float* o = g_xn + (size_t)(s * Bb + b) * Dd;
#pragma unroll
    for (int i = 0; i < 4; i++) { int d = t + 256 * i; o[d] = (v[i] - mu) * inv * sc[d] + bi[d]; }
}

__global__ __launch_bounds__(256) void k_ema(const float* __restrict__ de, const float* __restrict__ al,
                                             const float* __restrict__ be, const float* __restrict__ ga,
                                             const float* __restrict__ om) {
    int t = threadIdx.x, lane = t & 15;
    int P = blockIdx.x * 16 + (t >> 4), b = P / Dd, d = P % Dd;
    int pi = d * Nn + lane;
    float p = sigm(de[pi]);
    float q = 1.f - p * sigm(al[pi]);
    float coef = p * be[pi] * ga[pi] * 0.25f;
    float w = om[d];
    const float* xp = g_xn + (size_t)b * Dd + d;
    float* op = g_mx + (size_t)b * Dd + d;
    float s = 0.f;
    for (int l = 0; l < Ss; l++) {
        float xv = xp[(size_t)l * (Bb * Dd)];
        s = fmaf(q, s, xv);
        float r = coef * s;
        r += __shfl_xor_sync(~0u, r, 1);
        r += __shfl_xor_sync(~0u, r, 2);
        r += __shfl_xor_sync(~0u, r, 4);
        r += __shfl_xor_sync(~0u, r, 8);
        if (lane == 0) op[(size_t)l * (Bb * Dd)] = silu(r + xv * w);
    }
}

__global__ __launch_bounds__(256) void k_softmax() {
    float* rp = g_sc + (size_t)blockIdx.x * Ss;
    int t = threadIdx.x;
    float v[8], mx = -1e30f;
#pragma unroll
    for (int i = 0; i < 8; i++) { v[i] = rp[t + 256 * i]; mx = fmaxf(mx, v[i]); }
    mx = blockMax1(mx);
    float su = 0.f;
#pragma unroll
    for (int i = 0; i < 8; i++) { v[i] = __expf(v[i] - mx); su += v[i]; }
    su = blockSum1(su);
    float inv = 1.f / su;
#pragma unroll
    for (int i = 0; i < 8; i++) rp[t + 256 * i] = v[i] * inv;
}

__global__ __launch_bounds__(256) void k_gateln(const float* __restrict__ sc,
                                                const float* __restrict__ bi) {
    int m = blockIdx.x, s = m >> 3, b = m & 7, t = threadIdx.x;
    size_t base = (size_t)m * Dd;
    float g[4], su = 0.f, sq = 0.f;
#pragma unroll
    for (int i = 0; i < 4; i++) {
        int d = t + 256 * i;
        float xn = g_xn[base + d];
        float val = xn + g_u[base + d] * (g_h2[base + d] - xn);
        g[i] = val; su += val; sq += val * val;
    }
    blockSum2(su, sq);
    float mu = su * (1.f / Dd), inv = rsqrtf(sq * (1.f / Dd) - mu * mu + EPS);
    float* o = g_ol + ((size_t)b * Ss + s) * Dd;
#pragma unroll
    for (int i = 0; i < 4; i++) { int d = t + 256 * i; o[d] = (g[i] - mu) * inv * sc[d] + bi[d]; }
}

__global__ __launch_bounds__(256) void k_wt(const float* __restrict__ W,
                                            __nv_bfloat16* __restrict__ oh,
                                            __nv_bfloat16* __restrict__ ol, int K, int N) {
    __shared__ float tl[32][33];
    int n0 = blockIdx.x * 32, k0 = blockIdx.y * 32;
    int tx = threadIdx.x & 31, ty = threadIdx.x >> 5;
#pragma unroll
    for (int i = 0; i < 4; i++) tl[ty + i * 8][tx] = W[(size_t)(k0 + ty + i * 8) * N + n0 + tx];
    __syncthreads();
#pragma unroll
    for (int i = 0; i < 4; i++) {
        int ny = ty + i * 8;
        float v = tl[tx][ny];
        size_t o = (size_t)(n0 + ny) * K + k0 + tx;
        __nv_bfloat16 h = __float2bfloat16(v);
        oh[o] = h;
        ol[o] = __float2bfloat16(v - __bfloat162float(h));
    }
}

// ================= mma.sync bf16-split GEMM =================
struct TG {
    const float* A;
    const __nv_bfloat16* Bh; const __nv_bfloat16* Bl;
    const float* bias; const float* aux; const float* aux2;
    float* out;
    int K, Nv;          // Nv = valid N (epilogue/LDGB guard)
    long long sA, sB;   // per-batch strides
};

enum { MP_V = 0, MP_BASE, MP_SC, MP_HR, MP_H2, MP_RELU, MP_FIN };

template<int EP>
DEVFN void epiM(const TG& p, int bz, int m, int n, float acc) {
    if (EP == MP_V) {
        float v = silu(acc + p.bias[n]);
        int s = m >> 3, b = m & 7;
        size_t o = ((size_t)(b * Hh + n)) * Ss + s;   // v^T [B,H,S]
        __nv_bfloat16 h = __float2bfloat16(v);
        g_vh[o] = h;
        g_vl[o] = __float2bfloat16(v - __bfloat162float(h));
    } else if (EP == MP_BASE) {
        float a = acc + p.bias[n];
        if (n < Dd) {
            g_u[(size_t)m * Dd + n] = sigm(a);
        } else if (n < Dd + Zz) {
            float z = silu(a); int zi = n - Dd;
            int s = m >> 3, b = m & 7;
            size_t o = ((size_t)(b * Ss + s)) * Zz + zi;
            g_q[o] = z * p.aux[zi] + p.aux2[zi];
            float kv = z * p.aux[Zz + zi] + p.aux2[Zz + zi];
            __nv_bfloat16 h = __float2bfloat16(kv);
            g_kh[o] = h;
            g_kl[o] = __float2bfloat16(kv - __bfloat162float(h));
        } else if (n < Dd + Zz + Hh) {
            g_r[(size_t)m * Hh + (n - Dd - Zz)] = silu(a);
        } else {
            g_hx[(size_t)m * Dd + (n - Dd - Zz - Hh)] = a;
        }
    } else if (EP == MP_SC) {
        g_sc[((size_t)bz * Ss + m) * Ss + n] = acc * SCALING + p.aux[MPc - 1 + n - m];
    } else if (EP == MP_HR) {
        size_t o = ((size_t)(m * Bb + bz)) * Hh + n;
        g_hr[o] = acc * g_r[o];
    } else if (EP == MP_H2) {
        g_h2[(size_t)m * Dd + n] = silu(acc + p.bias[n] + g_hx[(size_t)m * Dd + n]);
    } else if (EP == MP_RELU) {
        g_in[(size_t)m * II + n] = fmaxf(acc + p.bias[n], 0.f);
    } else {
        p.out[(size_t)m * Dd + n] = acc + p.bias[n] + g_ol[(size_t)m * Dd + n];
    }
}

// CTA 128x256, warp 64x64 (8 warps), K-chunk 32 bf16, double-buffered smem.
// smem row = 16 b32 (64B); swizzle col_b32 ^ (2*(row&7)).  (PROVEN core, + batching + N-guard)
template<int EP>
__global__ void __launch_bounds__(256, 1) k_mgemm(TG p) {
    constexpr int TM = 128, TN = 256;
    constexpr int ASZ = TM * 64;
    constexpr int BSZ = TN * 64;
    constexpr int STGB = 2 * ASZ + 2 * BSZ;
    constexpr int IA = 8;
    constexpr int IB16 = 4;

    extern __shared__ char sm[];
    const unsigned sb = smem_u32(sm);

    const int t = threadIdx.x, lane = t & 31, wid = t >> 5;
    const int wm = wid & 1, wn = wid >> 1;
    const int g = lane >> 2, tig = lane & 3;
    const int bz = blockIdx.z;
    const int m0 = blockIdx.y * TM, n0 = blockIdx.x * TN;
    const float* A = p.A + (size_t)bz * (size_t)p.sA;
    const __nv_bfloat16* Bhp = p.Bh + (size_t)bz * (size_t)p.sB;
    const __nv_bfloat16* Blp = p.Bl + (size_t)bz * (size_t)p.sB;
    const int K = p.K;
    const int nst = K >> 5;
    const int Nv = p.Nv;

    float acc[4][8][4];
#pragma unroll
    for (int i = 0; i < 4; i++)
#pragma unroll
        for (int j = 0; j < 8; j++)
#pragma unroll
            for (int r = 0; r < 4; r++) acc[i][j][r] = 0.f;

    float2 rga[IA];
    uint4 rbh[IB16], rbl[IB16];

    auto LDGA = [&](int k0) {
#pragma unroll
        for (int j = 0; j < IA; j++) {
            int idx = t + 256 * j;
            int row = idx >> 4, c = idx & 15;
            rga[j] = *(const float2*)(A + (size_t)(m0 + row) * K + k0 + c * 2);
        }
    };
    auto LDGB = [&](int k0) {
#pragma unroll
        for (int j = 0; j < IB16; j++) {
            int idx = t + 256 * j;
            int row = idx >> 2, q = idx & 3;
            int rn = n0 + row; if (rn >= Nv) rn = Nv - 1;   // guard (only last mx tile)
            size_t go = (size_t)rn * K + k0 + q * 8;
            rbh[j] = *(const uint4*)(Bhp + go);
            rbl[j] = *(const uint4*)(Blp + go);
        }
    };
    auto STSA = [&](int buf) {
        unsigned base = sb + buf * STGB;
#pragma unroll
        for (int j = 0; j < IA; j++) {
            int idx = t + 256 * j;
            int row = idx >> 4, c = idx & 15;
            unsigned off = row * 64 + ((c ^ (2 * (row & 7))) << 2);
            float2 f = rga[j];
            __nv_bfloat162 h2 = __floats2bfloat162_rn(f.x, f.y);
            float2 hf = __bfloat1622float2(h2);
            __nv_bfloat162 l2 = __floats2bfloat162_rn(f.x - hf.x, f.y - hf.y);
            unsigned uh = *(unsigned*)&h2, ul = *(unsigned*)&l2;
            asm volatile("st.shared.b32 [%0], %1;" :: "r"(base + off), "r"(uh) : "memory");
            asm volatile("st.shared.b32 [%0], %1;" :: "r"(base + ASZ + off), "r"(ul) : "memory");
        }
    };
    auto STSB = [&](int buf) {
        unsigned bh = sb + buf * STGB + 2 * ASZ;
        unsigned bl = bh + BSZ;
#pragma unroll
        for (int j = 0; j < IB16; j++) {
            int idx = t + 256 * j;
            int row = idx >> 2, q = idx & 3;
            int c0 = q * 4;
            unsigned sw = 2 * (row & 7);
            unsigned o0 = row * 64 + ((c0 ^ sw) << 2);
            unsigned o1 = row * 64 + (((c0 + 2) ^ sw) << 2);
            uint4 h = rbh[j], l = rbl[j];
            asm volatile("st.shared.v2.b32 [%0], {%1,%2};" :: "r"(bh + o0), "r"(h.x), "r"(h.y) : "memory");
            asm volatile("st.shared.v2.b32 [%0], {%1,%2};" :: "r"(bh + o1), "r"(h.z), "r"(h.w) : "memory");
            asm volatile("st.shared.v2.b32 [%0], {%1,%2};" :: "r"(bl + o0), "r"(l.x), "r"(l.y) : "memory");
            asm volatile("st.shared.v2.b32 [%0], {%1,%2};" :: "r"(bl + o1), "r"(l.z), "r"(l.w) : "memory");
        }
    };

    auto COMPUTE = [&](int buf) {
        unsigned aB = sb + buf * STGB + (wm * 64) * 64;
        unsigned bB = sb + buf * STGB + 2 * ASZ + (wn * 64) * 64;
        const unsigned sw = 2 * g;
#pragma unroll
        for (int kk = 0; kk < 2; kk++) {
            const int kb = kk * 8;
            const unsigned o0 = (((kb + tig) ^ sw) << 2);
            const unsigned o2 = (((kb + tig + 4) ^ sw) << 2);
            unsigned Ah[4][4], Al[4][4];
#pragma unroll
            for (int mi = 0; mi < 4; mi++) {
                unsigned r0 = aB + (mi * 16 + g) * 64;
                asm volatile("ld.shared.b32 %0, [%1];" : "=r"(Ah[mi][0]) : "r"(r0 + o0));
                asm volatile("ld.shared.b32 %0, [%1];" : "=r"(Ah[mi][1]) : "r"(r0 + 512 + o0));
                asm volatile("ld.shared.b32 %0, [%1];" : "=r"(Ah[mi][2]) : "r"(r0 + o2));
                asm volatile("ld.shared.b32 %0, [%1];" : "=r"(Ah[mi][3]) : "r"(r0 + 512 + o2));
                asm volatile("ld.shared.b32 %0, [%1];" : "=r"(Al[mi][0]) : "r"(r0 + ASZ + o0));
                asm volatile("ld.shared.b32 %0, [%1];" : "=r"(Al[mi][1]) : "r"(r0 + ASZ + 512 + o0));
                asm volatile("ld.shared.b32 %0, [%1];" : "=r"(Al[mi][2]) : "r"(r0 + ASZ + o2));
                asm volatile("ld.shared.b32 %0, [%1];" : "=r"(Al[mi][3]) : "r"(r0 + ASZ + 512 + o2));
            }
#pragma unroll
            for (int nh = 0; nh < 2; nh++) {
                unsigned Bhf[4][2], Blf[4][2];
#pragma unroll
                for (int nj = 0; nj < 4; nj++) {
                    unsigned rn = bB + (nh * 32 + nj * 8 + g) * 64;
                    asm volatile("ld.shared.b32 %0, [%1];" : "=r"(Bhf[nj][0]) : "r"(rn + o0));
                    asm volatile("ld.shared.b32 %0, [%1];" : "=r"(Bhf[nj][1]) : "r"(rn + o2));
                    asm volatile("ld.shared.b32 %0, [%1];" : "=r"(Blf[nj][0]) : "r"(rn + BSZ + o0));
                    asm volatile("ld.shared.b32 %0, [%1];" : "=r"(Blf[nj][1]) : "r"(rn + BSZ + o2));
                }
#pragma unroll
                for (int mi = 0; mi < 4; mi++)
#pragma unroll
                    for (int nj = 0; nj < 4; nj++) {
                        float* c = acc[mi][nh * 4 + nj];
                        mma16816(c, Ah[mi], Bhf[nj]);
                        mma16816(c, Al[mi], Bhf[nj]);
                        mma16816(c, Ah[mi], Blf[nj]);
                    }
            }
        }
    };

    LDGA(0); LDGB(0);
    STSA(0); STSB(0);
    __syncthreads();

    for (int s = 0; s < nst; s++) {
        if (s + 1 < nst) { LDGA((s + 1) * 32); LDGB((s + 1) * 32); }
        COMPUTE(s & 1);
        if (s + 1 < nst) { STSA((s + 1) & 1); STSB((s + 1) & 1); }
        __syncthreads();
    }

#pragma unroll
    for (int mi = 0; mi < 4; mi++)
#pragma unroll
        for (int ni = 0; ni < 8; ni++) {
            int row0 = m0 + wm * 64 + mi * 16 + g;
            int col0 = n0 + wn * 64 + ni * 8 + 2 * tig;
            float* c = acc[mi][ni];
            if (col0 < Nv)     epiM<EP>(p, bz, row0,     col0,     c[0]);
            if (col0 + 1 < Nv) epiM<EP>(p, bz, row0,     col0 + 1, c[1]);
            if (col0 < Nv)     epiM<EP>(p, bz, row0 + 8, col0,     c[2]);
            if (col0 + 1 < Nv) epiM<EP>(p, bz, row0 + 8, col0 + 1, c[3]);
        }
}

// ---------------- launch ----------------
constexpr int SM256 = 2 * (2 * 128 * 64 + 2 * 256 * 64);  // 98304

extern "C" void kernel_launch(void* const* d_in, const int* in_sizes, int n_in,
                              void* d_out, int out_size) {
    (void)in_sizes; (void)n_in; (void)out_size;
    const float* x    = (const float*)d_in[0];
    const float* ln_s = (const float*)d_in[1];
    const float* ln_b = (const float*)d_in[2];
    const float* v_w  = (const float*)d_in[3];
    const float* v_b  = (const float*)d_in[4];
    const float* mx_w = (const float*)d_in[5];
    const float* mx_b = (const float*)d_in[6];
    const float* h_w  = (const float*)d_in[7];
    const float* h_b  = (const float*)d_in[8];
    const float* gamma= (const float*)d_in[9];
    const float* beta = (const float*)d_in[10];
    const float* rel  = (const float*)d_in[11];
    const float* e_d  = (const float*)d_in[12];
    const float* e_a  = (const float*)d_in[13];
    const float* e_b  = (const float*)d_in[14];
    const float* e_g  = (const float*)d_in[15];
    const float* e_o  = (const float*)d_in[16];
    const float* f_s  = (const float*)d_in[17];
    const float* f_b  = (const float*)d_in[18];
    const float* w1   = (const float*)d_in[19];
    const float* b1   = (const float*)d_in[20];
    const float* w2   = (const float*)d_in[21];
    const float* b2   = (const float*)d_in[22];

    float *p_xn, *p_mx, *p_q, *p_sc, *p_hr, *p_ol, *p_in;
    __nv_bfloat16 *p_kh, *p_kl, *p_vh, *p_vl;
    __nv_bfloat16 *p_wvh, *p_wvl, *p_wmh, *p_wml, *p_whh, *p_whl, *p_w1h, *p_w1l, *p_w2h, *p_w2l;
    cudaGetSymbolAddress((void**)&p_xn, g_xn);
    cudaGetSymbolAddress((void**)&p_mx, g_mx);
    cudaGetSymbolAddress((void**)&p_q,  g_q);
    cudaGetSymbolAddress((void**)&p_sc, g_sc);
    cudaGetSymbolAddress((void**)&p_hr, g_hr);
    cudaGetSymbolAddress((void**)&p_ol, g_ol);
    cudaGetSymbolAddress((void**)&p_in, g_in);
    cudaGetSymbolAddress((void**)&p_kh, g_kh);
    cudaGetSymbolAddress((void**)&p_kl, g_kl);
    cudaGetSymbolAddress((void**)&p_vh, g_vh);
    cudaGetSymbolAddress((void**)&p_vl, g_vl);
    cudaGetSymbolAddress((void**)&p_wvh, g_wvh);
    cudaGetSymbolAddress((void**)&p_wvl, g_wvl);
    cudaGetSymbolAddress((void**)&p_wmh, g_wmh);
    cudaGetSymbolAddress((void**)&p_wml, g_wml);
    cudaGetSymbolAddress((void**)&p_whh, g_whh);
    cudaGetSymbolAddress((void**)&p_whl, g_whl);
    cudaGetSymbolAddress((void**)&p_w1h, g_w1h);
    cudaGetSymbolAddress((void**)&p_w1l, g_w1l);
    cudaGetSymbolAddress((void**)&p_w2h, g_w2h);
    cudaGetSymbolAddress((void**)&p_w2l, g_w2l);

    cudaFuncSetAttribute(k_mgemm<MP_V>,    cudaFuncAttributeMaxDynamicSharedMemorySize, SM256);
    cudaFuncSetAttribute(k_mgemm<MP_BASE>, cudaFuncAttributeMaxDynamicSharedMemorySize, SM256);
    cudaFuncSetAttribute(k_mgemm<MP_SC>,   cudaFuncAttributeMaxDynamicSharedMemorySize, SM256);
    cudaFuncSetAttribute(k_mgemm<MP_HR>,   cudaFuncAttributeMaxDynamicSharedMemorySize, SM256);
    cudaFuncSetAttribute(k_mgemm<MP_H2>,   cudaFuncAttributeMaxDynamicSharedMemorySize, SM256);
    cudaFuncSetAttribute(k_mgemm<MP_RELU>, cudaFuncAttributeMaxDynamicSharedMemorySize, SM256);
    cudaFuncSetAttribute(k_mgemm<MP_FIN>,  cudaFuncAttributeMaxDynamicSharedMemorySize, SM256);

    // weight prep
    k_wt<<<dim3(Hh / 32, Dd / 32), 256>>>(v_w, p_wvh, p_wvl, Dd, Hh);
    k_wt<<<dim3(NMX / 32, Dd / 32), 256>>>(mx_w, p_wmh, p_wml, Dd, NMX);
    k_wt<<<dim3(Dd / 32, Hh / 32), 256>>>(h_w, p_whh, p_whl, Hh, Dd);
    k_wt<<<dim3(II / 32, Dd / 32), 256>>>(w1, p_w1h, p_w1l, Dd, II);
    k_wt<<<dim3(Dd / 32, II / 32), 256>>>(w2, p_w2h, p_w2l, II, Dd);

    k_ln1<<<SB, 256>>>(x, ln_s, ln_b);
    k_ema<<<(Bb * Dd) / 16, 256>>>(e_d, e_a, e_b, e_g, e_o);

    TG p;
    // v = silu(xn @ v_w + v_b) -> v^T bf16 split
    p = {p_xn, p_wvh, p_wvl, v_b, nullptr, nullptr, nullptr, Dd, Hh, 0, 0};
    k_mgemm<MP_V><<<dim3(Hh / 256, SB / 128, 1), 256, SM256>>>(p);
    // base = mx @ mx_w + mx_b -> u,(q,k),r,hx   (17 guarded 256-wide tiles over N=4224)
    p = {p_mx, p_wmh, p_wml, mx_b, gamma, beta, nullptr, Dd, NMX, 0, 0};
    k_mgemm<MP_BASE><<<dim3((NMX + 255) / 256, SB / 128, 1), 256, SM256>>>(p);
    // scores = scaling * q @ k^T + relpos   (batched)
    p = {p_q, p_kh, p_kl, nullptr, rel, nullptr, nullptr, Zz, Ss, (long long)Ss * Zz, (long long)Ss * Zz};
    k_mgemm<MP_SC><<<dim3(Ss / 256, Ss / 128, Bb), 256, SM256>>>(p);
    k_softmax<<<Bb * Ss, 256>>>();
    // hr = (attn @ v) * r   (batched, fused)
    p = {p_sc, p_vh, p_vl, nullptr, nullptr, nullptr, nullptr, Ss, Hh, (long long)Ss * Ss, (long long)Hh * Ss};
    k_mgemm<MP_HR><<<dim3(Hh / 256, Ss / 128, Bb), 256, SM256>>>(p);
    // h2 = silu(hx + hr @ h_w + h_b)
    p = {p_hr, p_whh, p_whl, h_b, nullptr, nullptr, nullptr, Hh, Dd, 0, 0};
    k_mgemm<MP_H2><<<dim3(Dd / 256, SB / 128, 1), 256, SM256>>>(p);
    k_gateln<<<SB, 256>>>(f_s, f_b);
    // FFN
    p = {p_ol, p_w1h, p_w1l, b1, nullptr, nullptr, nullptr, Dd, II, 0, 0};
    k_mgemm<MP_RELU><<<dim3(II / 256, SB / 128, 1), 256, SM256>>>(p);
    p = {p_in, p_w2h, p_w2l, b2, nullptr, nullptr, (float*)d_out, II, Dd, 0, 0};
    k_mgemm<MP_FIN><<<dim3(Dd / 256, SB / 128, 1), 256, SM256>>>(p);
}